// round 17
// baseline (speedup 1.0000x reference)
#include <cuda_runtime.h>
#include <cuda_bf16.h>
#include <math.h>
#include <stdint.h>

#define Bn   8
#define Cc   256
#define C2   512
#define Hh   128
#define Ww   128
#define HW   16384
#define BHW  131072
#define HID  64

// Scratch (device globals: allocation-free rule)
__device__ float g_off[(size_t)BHW * 4];
__device__ float g_wfrag[C2 / 8 * 512];       // p1 weights in tf32 mma B-fragment order
__device__ float g_p2eff[HID * 4];
__device__ float g_p2beff[4];
__device__ float g_pooled[Bn * C2];
__device__ float g_mod[Bn * Cc];
__device__ float g_qpart[16][(size_t)BHW];    // per (quarter,ch-group) quality partials

// ---- cp.async helpers ----
__device__ __forceinline__ uint32_t smem_u32(const void* p) {
    return (uint32_t)__cvta_generic_to_shared(p);
}
__device__ __forceinline__ void cpa4(uint32_t dst, const float* src, int sz) {
    asm volatile("cp.async.ca.shared.global [%0], [%1], 4, %2;" :: "r"(dst), "l"(src), "r"(sz));
}
__device__ __forceinline__ void cpa16(uint32_t dst, const float* src, int sz) {
    asm volatile("cp.async.ca.shared.global [%0], [%1], 16, %2;" :: "r"(dst), "l"(src), "r"(sz));
}
__device__ __forceinline__ void cpa_commit() { asm volatile("cp.async.commit_group;"); }
__device__ __forceinline__ void cpa_wait2() { asm volatile("cp.async.wait_group 2;"); }
__device__ __forceinline__ void cpa_wait1() { asm volatile("cp.async.wait_group 1;"); }
__device__ __forceinline__ void cpa_wait0() { asm volatile("cp.async.wait_group 0;"); }

// ---- tf32 mma ----
#define MMA_TF32(D, A, B0, B1) \
    asm volatile("mma.sync.aligned.m16n8k8.row.col.f32.tf32.tf32.f32 " \
        "{%0,%1,%2,%3}, {%4,%5,%6,%7}, {%8,%9}, {%0,%1,%2,%3};" \
        : "+f"((D)[0]), "+f"((D)[1]), "+f"((D)[2]), "+f"((D)[3]) \
        : "r"((A)[0]), "r"((A)[1]), "r"((A)[2]), "r"((A)[3]), "r"(B0), "r"(B1))

// ---------------- prep: pack p1 weights into mma B-fragment order, fold p2, zero pooled ----------------
__global__ void prep_kernel(const float* __restrict__ p1w,
                            const float* __restrict__ p2w,
                            const float* __restrict__ p2b) {
    int idx = blockIdx.x * 256 + threadIdx.x;
    if (idx < 64 * 512) {
        int chunk = idx >> 9, rem = idx & 511;
        int q = rem >> 7, lrem = rem & 127;
        int ll = lrem >> 2, jj = lrem & 3;
        int j = q * 4 + jj, t = j >> 1, r = j & 1;
        int n = t * 8 + (ll >> 2);
        int k = chunk * 8 + (ll & 3) + r * 4;
        float v = p1w[n * 512 + k];
        uint32_t tf;
        asm("cvt.rna.tf32.f32 %0, %1;" : "=r"(tf) : "f"(v));
        g_wfrag[idx] = __uint_as_float(tf);
    }
    if (idx < Bn * C2) g_pooled[idx] = 0.f;
    if (blockIdx.x == 0) {
        const float SC = 0.1f * 0.5f * 127.0f * 0.25f;
        if (threadIdx.x < HID) {
            int h = threadIdx.x;
            g_p2eff[h*4+0] = SC*(p2w[0*HID+h]+p2w[2*HID+h]+p2w[4*HID+h]+p2w[6*HID+h]);
            g_p2eff[h*4+1] = SC*(p2w[1*HID+h]+p2w[3*HID+h]+p2w[5*HID+h]+p2w[7*HID+h]);
            g_p2eff[h*4+2] = SC*(p2w[8*HID+h]+p2w[10*HID+h]+p2w[12*HID+h]+p2w[14*HID+h]);
            g_p2eff[h*4+3] = SC*(p2w[9*HID+h]+p2w[11*HID+h]+p2w[13*HID+h]+p2w[15*HID+h]);
        } else if (threadIdx.x < HID + 4) {
            int j = threadIdx.x - HID;
            int base = (j >> 1) * 8 + (j & 1);  // 0,1,8,9
            g_p2beff[j] = SC*(p2b[base]+p2b[base+2]+p2b[base+4]+p2b[base+6]);
        }
    }
}

// ---------------- modulation (runs AFTER dwgemm; pooled holds raw sums) ----------------
__global__ void mod_kernel(const float* __restrict__ m1w, const float* __restrict__ m1b,
                           const float* __restrict__ m2w, const float* __restrict__ m2b) {
    int b = blockIdx.x;
    __shared__ float hid[HID];
    __shared__ float pl[C2];
    for (int i = threadIdx.x; i < C2; i += 256)
        pl[i] = g_pooled[b * C2 + i] * (1.0f / (float)HW);
    __syncthreads();
    if (threadIdx.x < HID) {
        float s = m1b[threadIdx.x];
        const float* wr = m1w + threadIdx.x * C2;
        for (int c = 0; c < C2; c++) s = fmaf(wr[c], pl[c], s);
        hid[threadIdx.x] = fmaxf(s, 0.f);
    }
    __syncthreads();
    int o = threadIdx.x;
    float s = m2b[o];
    const float* wr = m2w + o * HID;
    #pragma unroll
    for (int h = 0; h < HID; h++) s = fmaf(wr[h], hid[h], s);
    g_mod[b * Cc + o] = 1.f / (1.f + expf(-s));
}

// ---------------- FUSED: depthwise 3x3 + GAP + tf32 tensor-core p1 GEMM + folded p2 ----------------
#define TW 32
#define TH 8
#define ROWF 44
#define CHT  440           // 10 * 44
#define TILEF (8 * CHT)    // 3520 floats per chunk buffer
#define CHK 8
#define NCHUNK (C2 / CHK)
#define NCP 800            // 16B granules per chunk (8ch * 10r * 10)
#define CHP 264            // XS channel stride (floats)

// dynamic smem layout (floats)
#define OFF_TILES 0                        // [4][3520]
#define OFF_XS    (OFF_TILES + 4*TILEF)    // [2][8*264]
#define OFF_WB    (OFF_XS + 2*(8*CHP))     // [4][512]
#define OFF_WDW   (OFF_WB + 4*512)         // [512*12]
#define SMEM_FLOATS (OFF_WDW + C2*12)
#define SMEM_BYTES  (SMEM_FLOATS * 4)

__global__ __launch_bounds__(256, 2)
void dwgemm_kernel(const float* __restrict__ rgb, const float* __restrict__ tir,
                   const float* __restrict__ dww, const float* __restrict__ dwb,
                   const float* __restrict__ p1b) {
    extern __shared__ __align__(16) float sm[];
    float* TILES = sm + OFF_TILES;
    float* XS    = sm + OFF_XS;
    float* WB    = sm + OFF_WB;
    float* WDW   = sm + OFF_WDW;

    const int tid = threadIdx.x;
    const int tx0 = blockIdx.x * TW;
    const int ty0 = blockIdx.y * TH;
    const int b   = blockIdx.z;
    const int w = tid >> 5;    // warp id
    const int l = tid & 31;    // lane

    // ---- chunk-invariant loader addressing (16B granules) ----
    int ofs[4], doff[4];
    unsigned vmask = 0;
    #pragma unroll
    for (int sl = 0; sl < 4; sl++) {
        int i = sl * 256 + tid;
        bool have = (i < NCP);
        int ii = have ? i : 0;
        int ch = ii / 100, rem = ii - ch * 100;
        int r = rem / 10, ci = rem - r * 10;
        int gy = ty0 + r - 1;
        int gx0 = tx0 - 4 + ci * 4;
        bool in = have && (gy >= 0) && (gy < Hh) && (gx0 >= 0) && (gx0 <= Ww - 4);
        ofs[sl]  = in ? (ch * HW + gy * Ww + gx0) : 0;
        doff[sl] = (ch * CHT + r * ROWF + ci * 4) * 4;
        if (in) vmask |= 1u << sl;
    }

    const float* rbase = rgb + (size_t)b * Cc * HW;
    const float* tbase = tir + (size_t)b * Cc * HW;
    const uint32_t tiles_a = smem_u32(TILES);
    const uint32_t wb_a    = smem_u32(WB);
    const uint32_t wdw_a   = smem_u32(WDW);

    auto load_chunk = [&](int chunk, int bt) {
        const float* base = (chunk < 32 ? rbase : tbase) + (size_t)((chunk & 31) * CHK) * HW;
        uint32_t dst0 = tiles_a + bt * (TILEF * 4);
        #pragma unroll
        for (int sl = 0; sl < 4; sl++) {
            if (sl < 3 || tid < (NCP - 768)) {
                int in = (vmask >> sl) & 1;
                cpa16(dst0 + doff[sl], base + ofs[sl], in ? 16 : 0);
            }
        }
        if (tid < 128)
            cpa16(wb_a + (bt * 512 + tid * 4) * 4, g_wfrag + chunk * 512 + tid * 4, 16);
    };

    // stage B: thread = 8-px strip x 1 channel (warp w -> channel w of the chunk)
    // Also accumulates the tile's central-row sum for GAP (g_pooled).
    auto stageB = [&](int chunk, int bt, int xb) {
        const int py = l >> 2, pxx = (l & 3) * 8;
        const float* t0 = TILES + bt * TILEF + w * CHT + py * ROWF + pxx;
        const float* wd = WDW + chunk * (CHK * 12) + w * 12;
        float4 wa = *(const float4*)(wd);
        float4 wb = *(const float4*)(wd + 4);
        float2 wc = *(const float2*)(wd + 8);
        float o[8];
        #pragma unroll
        for (int j = 0; j < 8; j++) o[j] = wc.y;   // bias
        float csum = 0.f;
        #pragma unroll
        for (int r = 0; r < 3; r++) {
            const float* tr = t0 + r * ROWF;
            float v[10];
            v[0] = tr[3];
            float4 q1 = *(const float4*)(tr + 4);
            float4 q2 = *(const float4*)(tr + 8);
            v[9] = tr[12];
            v[1]=q1.x; v[2]=q1.y; v[3]=q1.z; v[4]=q1.w;
            v[5]=q2.x; v[6]=q2.y; v[7]=q2.z; v[8]=q2.w;
            float w0 = (r==0)?wa.x:(r==1)?wa.w:wb.z;
            float w1 = (r==0)?wa.y:(r==1)?wb.x:wb.w;
            float w2 = (r==0)?wa.z:(r==1)?wb.y:wc.x;
            #pragma unroll
            for (int j = 0; j < 8; j++)
                o[j] = fmaf(w0, v[j], fmaf(w1, v[j+1], fmaf(w2, v[j+2], o[j])));
            if (r == 1)
                csum = ((v[1]+v[2])+(v[3]+v[4])) + ((v[5]+v[6])+(v[7]+v[8]));
        }
        float* xp = XS + xb * (8 * CHP) + w * CHP + py * TW + pxx;
        *(float4*)xp       = make_float4(o[0], o[1], o[2], o[3]);
        *(float4*)(xp + 4) = make_float4(o[4], o[5], o[6], o[7]);
        #pragma unroll
        for (int oo = 16; oo; oo >>= 1) csum += __shfl_xor_sync(0xffffffffu, csum, oo);
        if (l == 0) atomicAdd(&g_pooled[b * C2 + chunk * CHK + w], csum);
    };

    float d[64];
    #pragma unroll
    for (int i = 0; i < 64; i++) d[i] = 0.f;

    // prologue: dw taps (once) + chunks 0,1,2 in flight
    for (int i = tid; i < C2 * 12; i += 256) {
        int c2 = i / 12, k = i - c2 * 12;
        const float* src = (k < 9) ? dww + c2 * 9 + k : dwb + c2;
        cpa4(wdw_a + i * 4, src, (k <= 9) ? 4 : 0);
    }
    load_chunk(0, 0); cpa_commit();
    load_chunk(1, 1); cpa_commit();
    load_chunk(2, 2); cpa_commit();
    cpa_wait2();                 // taps + chunk 0 resident
    __syncthreads();
    stageB(0, 0, 0);

    for (int chunk = 0; chunk < NCHUNK; chunk++) {
        if (chunk + 2 < NCHUNK) cpa_wait1();
        else                    cpa_wait0();
        __syncthreads();

        if (chunk + 3 < NCHUNK) { load_chunk(chunk + 3, (chunk + 3) & 3); cpa_commit(); }
        if (chunk + 1 < NCHUNK) stageB(chunk + 1, (chunk + 1) & 3, (chunk + 1) & 1);

        // ---- stage C: tensor GEMM on XS[chunk&1] with WB[chunk&3] ----
        const float* xbp = XS + (chunk & 1) * (8 * CHP);
        const float4* B4 = (const float4*)(WB + (chunk & 3) * 512);
        uint32_t a[2][4];
        const int c = l & 3, row = l >> 2;
        #pragma unroll
        for (int m = 0; m < 2; m++) {
            int px = w * 32 + m * 16 + row;
            a[m][0] = __float_as_uint(xbp[c * CHP + px]);
            a[m][1] = __float_as_uint(xbp[c * CHP + px + 8]);
            a[m][2] = __float_as_uint(xbp[(c + 4) * CHP + px]);
            a[m][3] = __float_as_uint(xbp[(c + 4) * CHP + px + 8]);
        }
        #pragma unroll
        for (int q = 0; q < 4; q++) {
            float4 B = B4[q * 32 + l];
            uint32_t b0a = __float_as_uint(B.x), b1a = __float_as_uint(B.y);
            uint32_t b0b = __float_as_uint(B.z), b1b = __float_as_uint(B.w);
            #pragma unroll
            for (int m = 0; m < 2; m++) {
                MMA_TF32(d + (m * 8 + 2 * q) * 4,     a[m], b0a, b1a);
                MMA_TF32(d + (m * 8 + 2 * q + 1) * 4, a[m], b0b, b1b);
            }
        }
    }

    // ---- Epilogue: bias + ReLU + folded p2, quad-reduce over hid lanes ----
    float4 oA[2], oB[2];
    #pragma unroll
    for (int m = 0; m < 2; m++) {
        oA[m] = make_float4(0.f, 0.f, 0.f, 0.f);
        oB[m] = make_float4(0.f, 0.f, 0.f, 0.f);
    }
    const float4* P2 = (const float4*)g_p2eff;
    #pragma unroll
    for (int t = 0; t < 8; t++) {
        int h0 = t * 8 + (l & 3) * 2;
        float4 e0 = P2[h0], e1 = P2[h0 + 1];
        float bb0 = p1b[h0], bb1 = p1b[h0 + 1];
        #pragma unroll
        for (int m = 0; m < 2; m++) {
            const float* dd = d + (m * 8 + t) * 4;
            float r0 = fmaxf(dd[0] + bb0, 0.f), r1 = fmaxf(dd[1] + bb1, 0.f);
            float r2 = fmaxf(dd[2] + bb0, 0.f), r3 = fmaxf(dd[3] + bb1, 0.f);
            oA[m].x += e0.x * r0 + e1.x * r1;  oA[m].y += e0.y * r0 + e1.y * r1;
            oA[m].z += e0.z * r0 + e1.z * r1;  oA[m].w += e0.w * r0 + e1.w * r1;
            oB[m].x += e0.x * r2 + e1.x * r3;  oB[m].y += e0.y * r2 + e1.y * r3;
            oB[m].z += e0.z * r2 + e1.z * r3;  oB[m].w += e0.w * r2 + e1.w * r3;
        }
    }
    #pragma unroll
    for (int m = 0; m < 2; m++) {
        #pragma unroll
        for (int o = 1; o <= 2; o <<= 1) {
            oA[m].x += __shfl_xor_sync(0xffffffffu, oA[m].x, o);
            oA[m].y += __shfl_xor_sync(0xffffffffu, oA[m].y, o);
            oA[m].z += __shfl_xor_sync(0xffffffffu, oA[m].z, o);
            oA[m].w += __shfl_xor_sync(0xffffffffu, oA[m].w, o);
            oB[m].x += __shfl_xor_sync(0xffffffffu, oB[m].x, o);
            oB[m].y += __shfl_xor_sync(0xffffffffu, oB[m].y, o);
            oB[m].z += __shfl_xor_sync(0xffffffffu, oB[m].z, o);
            oB[m].w += __shfl_xor_sync(0xffffffffu, oB[m].w, o);
        }
    }
    if ((l & 3) == 0) {
        float4 bo = make_float4(g_p2beff[0], g_p2beff[1], g_p2beff[2], g_p2beff[3]);
        int py = ty0 + w;
        size_t base = (size_t)b * HW + py * Ww + tx0;
        #pragma unroll
        for (int m = 0; m < 2; m++) {
            int cA = m * 16 + (l >> 2);
            float4 sA = make_float4(oA[m].x + bo.x, oA[m].y + bo.y, oA[m].z + bo.z, oA[m].w + bo.w);
            float4 sB = make_float4(oB[m].x + bo.x, oB[m].y + bo.y, oB[m].z + bo.z, oB[m].w + bo.w);
            ((float4*)g_off)[base + cA]     = sA;
            ((float4*)g_off)[base + cA + 8] = sB;
        }
    }
}

// ---------------- bilinear sample + mod: thread = 4 px x 16 ch ----------------
__global__ __launch_bounds__(128, 5)
void sample_kernel(const float* __restrict__ rgb, const float* __restrict__ tir,
                   float* __restrict__ out) {
    const int pg = threadIdx.x & 31;    // pixel group: x = pg*4 + j
    const int cg = threadIdx.x >> 5;    // channel group: 16 channels
    const int y = blockIdx.x;
    const int b = blockIdx.y;
    const int quar = blockIdx.z;        // 0..3 -> channels [quar*64, quar*64+64)
    const int c0 = quar * 64 + cg * 16;

    __shared__ float smod[64];
    if (threadIdx.x < 64) smod[threadIdx.x] = g_mod[b * Cc + quar * 64 + threadIdx.x];
    __syncthreads();

    const int x0p = pg * 4;
    const int hw = y * Ww + x0p;
    const int p = b * HW + hw;

    int i00r[4], i01r[4], i10r[4], i11r[4];
    int i00t[4], i01t[4], i10t[4], i11t[4];
    float w00r[4], w01r[4], w10r[4], w11r[4];
    float w00t[4], w01t[4], w10t[4], w11t[4];

    #pragma unroll
    for (int j = 0; j < 4; j++) {
        float4 off = ((const float4*)g_off)[p + j];
        float xf = (float)(x0p + j), yf = (float)y;

        float ixr = fminf(fmaxf(xf + off.x, 0.f), 127.f);
        float iyr = fminf(fmaxf(yf + off.y, 0.f), 127.f);
        float fx0 = floorf(ixr), fy0 = floorf(iyr);
        int x0 = (int)fx0, y0 = (int)fy0;
        int x1 = min(x0 + 1, 127), y1 = min(y0 + 1, 127);
        float wx = ixr - fx0, wy = iyr - fy0;
        float cx = 1.f - wx, cy = 1.f - wy;
        i00r[j] = y0*Ww + x0; i01r[j] = y0*Ww + x1;
        i10r[j] = y1*Ww + x0; i11r[j] = y1*Ww + x1;
        w00r[j] = cx*cy; w01r[j] = wx*cy; w10r[j] = cx*wy; w11r[j] = wx*wy;

        float ixt = fminf(fmaxf(xf + off.z, 0.f), 127.f);
        float iyt = fminf(fmaxf(yf + off.w, 0.f), 127.f);
        float gx0 = floorf(ixt), gy0 = floorf(iyt);
        int u0 = (int)gx0, v0 = (int)gy0;
        int u1 = min(u0 + 1, 127), v1 = min(v0 + 1, 127);
        float wxt = ixt - gx0, wyt = iyt - gy0;
        float cxt = 1.f - wxt, cyt = 1.f - wyt;
        i00t[j] = v0*Ww + u0; i01t[j] = v0*Ww + u1;
        i10t[j] = v1*Ww + u0; i11t[j] = v1*Ww + u1;
        w00t[j] = cxt*cyt; w01t[j] = wxt*cyt; w10t[j] = cxt*wyt; w11t[j] = wxt*wyt;
    }

    const float* rb = rgb + ((size_t)b * Cc + c0) * HW;
    const float* tb = tir + ((size_t)b * Cc + c0) * HW;
    float* outR = out + ((size_t)b * Cc + c0) * HW + hw;
    float* outT = out + (size_t)Bn * Cc * HW + ((size_t)b * Cc + c0) * HW + hw;

    float4 qv = make_float4(0.f, 0.f, 0.f, 0.f);
    float* qa = &qv.x;

    #pragma unroll 2
    for (int c = 0; c < 16; c++) {
        size_t co = (size_t)c * HW;
        float md = smod[cg * 16 + c];
        float rv[4], tv[4];
        #pragma unroll
        for (int j = 0; j < 4; j++) {
            float v00 = rb[co + i00r[j]], v01 = rb[co + i01r[j]];
            float v10 = rb[co + i10r[j]], v11 = rb[co + i11r[j]];
            rv[j] = (v00*w00r[j] + v01*w01r[j] + v10*w10r[j] + v11*w11r[j]) * md;
            float u00 = tb[co + i00t[j]], u01 = tb[co + i01t[j]];
            float u10 = tb[co + i10t[j]], u11 = tb[co + i11t[j]];
            tv[j] = (u00*w00t[j] + u01*w01t[j] + u10*w10t[j] + u11*w11t[j]) * md;
            qa[j] += fabsf(rv[j] - tv[j]);
        }
        *(float4*)(outR + co) = make_float4(rv[0], rv[1], rv[2], rv[3]);
        *(float4*)(outT + co) = make_float4(tv[0], tv[1], tv[2], tv[3]);
    }
    *(float4*)&g_qpart[quar * 4 + cg][p] = qv;
}

// ---------------- quality epilogue ----------------
__global__ void qual_kernel(float* __restrict__ out) {
    int p = blockIdx.x * 256 + threadIdx.x;
    float s = 0.f;
    #pragma unroll
    for (int i = 0; i < 16; i++) s += g_qpart[i][p];
    float q = 1.f - s * (1.f / (float)Cc);
    out[(size_t)2 * Bn * Cc * HW + p] = 1.f / (1.f + expf(-q));
}

extern "C" void kernel_launch(void* const* d_in, const int* in_sizes, int n_in,
                              void* d_out, int out_size) {
    const float* rgb  = (const float*)d_in[0];
    const float* tir  = (const float*)d_in[1];
    const float* dw_w = (const float*)d_in[2];
    const float* dw_b = (const float*)d_in[3];
    const float* p1_w = (const float*)d_in[4];
    const float* p1_b = (const float*)d_in[5];
    const float* p2_w = (const float*)d_in[6];
    const float* p2_b = (const float*)d_in[7];
    const float* m1_w = (const float*)d_in[8];
    const float* m1_b = (const float*)d_in[9];
    const float* m2_w = (const float*)d_in[10];
    const float* m2_b = (const float*)d_in[11];
    float* out = (float*)d_out;

    cudaFuncSetAttribute(dwgemm_kernel, cudaFuncAttributeMaxDynamicSharedMemorySize, SMEM_BYTES);

    prep_kernel<<<129, 256>>>(p1_w, p2_w, p2_b);
    dwgemm_kernel<<<dim3(Ww / TW, Hh / TH, Bn), 256, SMEM_BYTES>>>(rgb, tir, dw_w, dw_b, p1_b);
    mod_kernel<<<Bn, 256>>>(m1_w, m1_b, m2_w, m2_b);
    sample_kernel<<<dim3(Hh, Bn, 4), 128>>>(rgb, tir, out);
    qual_kernel<<<BHW / 256, 256>>>(out);
}